// round 1
// baseline (speedup 1.0000x reference)
#include <cuda_runtime.h>
#include <math.h>

// Problem constants
#define BB 8
#define NN 1024
#define FF 128
#define GG 64
#define MM 4
#define EE 3
#define BE (BB*EE)        // 24
#define SLOTS (MM*GG)     // 256
#define ROWS (BB*NN)      // 8192
#define HC (MM*EE*GG)     // 768
#define L0C 256
#define L1C 256

// ---------------- scratch (__device__ globals; no allocation allowed) ----------------
__device__ float d_Wt[EE*FF*SLOTS];          // 98304  : Ws re-laid-out [e][f][m*64+g]
__device__ float d_Wh[BE*NN*SLOTS];          // 6.29M  : [be][n][m*64+g]
__device__ float d_s1[BE*MM*NN];             // 98304  : [be][m][n]
__device__ float d_s2[BE*MM*NN];
__device__ float d_H [ROWS*HC];              // 6.29M  : [b*N+n][m*192+e*64+g]
__device__ float d_Hn[ROWS*FF];              // bn1 output (needed twice)
__device__ float d_bufA[ROWS*L0C];           // ping
__device__ float d_bufB[ROWS*L0C];           // pong
__device__ float d_stats[4*512];             // 4 layers x (sum[256] | sumsq[256])

// ---------------- tiny utility kernels ----------------
__global__ void zero_kernel(float* p, int n) {
    int i = blockIdx.x*blockDim.x + threadIdx.x;
    if (i < n) p[i] = 0.f;
}

// Wt[e][f][m*64+g] = Ws[e][(m*128+f)*64+g]
__global__ void wt_kernel(const float* __restrict__ Ws, float* __restrict__ Wt) {
    int idx = blockIdx.x*blockDim.x + threadIdx.x;
    if (idx >= EE*FF*SLOTS) return;
    int e = idx >> 15;              // /32768
    int r = idx & 32767;
    int f = r >> 8;                 // /256
    int c = r & 255;
    int m = c >> 6, g = c & 63;
    Wt[idx] = Ws[e*32768 + m*8192 + f*64 + g];
}

// edge_cat[b,i,j,e] = (float)A[b,e,i,j]; 16 j per thread, coalesced float4 stores
__global__ void edge_kernel(const int* __restrict__ A, float* __restrict__ out) {
    int idx = blockIdx.x*blockDim.x + threadIdx.x;
    if (idx >= BB*NN*(NN/16)) return;
    int j0 = (idx & 63) << 4;       // N/16 = 64 chunks
    int bi = idx >> 6;              // b*N + i
    int b = bi >> 10, i = bi & 1023;
    float v[48];
#pragma unroll
    for (int e = 0; e < 3; e++) {
        const int4* src = (const int4*)(A + (((long)(b*3+e)*NN + i) << 10) + j0);
#pragma unroll
        for (int k = 0; k < 4; k++) {
            int4 a = src[k];
            v[(k*4+0)*3+e] = (float)a.x;
            v[(k*4+1)*3+e] = (float)a.y;
            v[(k*4+2)*3+e] = (float)a.z;
            v[(k*4+3)*3+e] = (float)a.w;
        }
    }
    float4* o = (float4*)(out + (long)bi*3072 + (long)j0*3);
#pragma unroll
    for (int k = 0; k < 12; k++) o[k] = ((float4*)v)[k];
}

// s1[be][m][n] = sum_g Wh[be][n][m*64+g]*a1[e][m*64+g]; warp per (be,n)
__global__ void s_kernel(const float* __restrict__ Wh, const float* __restrict__ a1,
                         const float* __restrict__ a2,
                         float* __restrict__ s1, float* __restrict__ s2) {
    int gtid = blockIdx.x*blockDim.x + threadIdx.x;
    int wid = gtid >> 5;
    int lane = gtid & 31;
    if (wid >= BE*NN) return;
    int be = wid >> 10;
    int n  = wid & 1023;
    int e  = be % 3;
    const float4* w  = (const float4*)(Wh + (long)wid*SLOTS);
    const float4* A1 = (const float4*)(a1 + e*SLOTS);
    const float4* A2 = (const float4*)(a2 + e*SLOTS);
    float4 wa = w[lane*2], wb = w[lane*2+1];
    float4 p1a = A1[lane*2], p1b = A1[lane*2+1];
    float4 p2a = A2[lane*2], p2b = A2[lane*2+1];
    float d1 = wa.x*p1a.x + wa.y*p1a.y + wa.z*p1a.z + wa.w*p1a.w
             + wb.x*p1b.x + wb.y*p1b.y + wb.z*p1b.z + wb.w*p1b.w;
    float d2 = wa.x*p2a.x + wa.y*p2a.y + wa.z*p2a.z + wa.w*p2a.w
             + wb.x*p2b.x + wb.y*p2b.y + wb.z*p2b.z + wb.w*p2b.w;
#pragma unroll
    for (int off = 4; off > 0; off >>= 1) {
        d1 += __shfl_down_sync(0xffffffffu, d1, off, 8);
        d2 += __shfl_down_sync(0xffffffffu, d2, off, 8);
    }
    if ((lane & 7) == 0) {
        int m = lane >> 3;
        s1[(be*4+m)*NN + n] = d1;
        s2[(be*4+m)*NN + n] = d2;
    }
}

// ---------------- attention: fused masked softmax + P@Wh (all 4 heads) ----------------
// grid (32, 24): blockIdx.y = be, blockIdx.x = i-tile of 32 rows. 256 threads.
// smem: sWh[32][256] (32KB) | sP[m][32 i][32 j] (16KB) | sDen[32 i][4 m][8 jg] (4KB)
__global__ void __launch_bounds__(256) att_kernel(
        const int* __restrict__ A, const float* __restrict__ Wh,
        const float* __restrict__ s1, const float* __restrict__ s2,
        float* __restrict__ H) {
    extern __shared__ float sm[];
    float* sWh  = sm;            // 8192 floats
    float* sP   = sm + 8192;     // 4096 floats
    float* sDen = sm + 12288;    // 1024 floats

    const int be = blockIdx.y;
    const int b  = be / 3, e = be % 3;
    const int i0 = blockIdx.x * 32;
    const int t  = threadIdx.x;

    // p-phase mapping
    const int ip = t >> 3;        // 0..31 (row)
    const int jg = t & 7;         // 0..7  (4 j's each)
    // accumulate-phase mapping
    const int ig = t >> 5;        // warp 0..7 -> rows ig*4..+3
    const int sg = t & 31;
    const int am = sg >> 3;       // head
    const int g0 = (sg & 7) * 8;  // g-chunk

    float s1v[4];
#pragma unroll
    for (int m = 0; m < 4; m++) s1v[m] = s1[(be*4+m)*NN + i0 + ip];

    float den[4] = {0.f,0.f,0.f,0.f};
    float acc[4][8];
#pragma unroll
    for (int ii = 0; ii < 4; ii++)
#pragma unroll
        for (int q = 0; q < 8; q++) acc[ii][q] = 0.f;

    const int*   Arow   = A  + ((long)be*NN + i0 + ip)*NN;
    const float4* WhB   = (const float4*)(Wh + (long)be*NN*SLOTS);
    const float* s2base = s2 + be*4*NN;

    for (int j0 = 0; j0 < NN; j0 += 32) {
        __syncthreads();   // previous accumulate done before smem reuse
        // load Wh tile [32 j][256 slots]
        {
            const float4* src = WhB + (long)j0*64;
            float4* dst = (float4*)sWh;
#pragma unroll
            for (int k = 0; k < 8; k++) dst[t + k*256] = src[t + k*256];
        }
        // masked exp(lrelu(s1+s2)) for 4 heads x 4 j
        {
            int4 mk = *(const int4*)(Arow + j0 + jg*4);
            int mv[4] = {mk.x, mk.y, mk.z, mk.w};
#pragma unroll
            for (int m = 0; m < 4; m++) {
                float pv[4];
#pragma unroll
                for (int q = 0; q < 4; q++) {
                    float sv = s2base[m*NN + j0 + jg*4 + q];
                    float x = s1v[m] + sv;
                    float l = (x >= 0.f) ? x : 0.01f*x;
                    float p = (mv[q] > 0) ? __expf(l) : 0.f;
                    pv[q] = p;
                    den[m] += p;
                }
                *(float4*)&sP[(m*32 + ip)*32 + jg*4] =
                    make_float4(pv[0], pv[1], pv[2], pv[3]);
            }
        }
        __syncthreads();
        // accumulate: acc[ii][q] += p[i][m] * Wh[j][m*64+g0+q]
        {
            const float* prow = sP + (am*32 + ig*4)*32;
#pragma unroll 4
            for (int j = 0; j < 32; j++) {
                const float* wrow = sWh + j*256 + am*64 + g0;
                float4 w0 = *(const float4*)(wrow);
                float4 w1 = *(const float4*)(wrow + 4);
#pragma unroll
                for (int ii = 0; ii < 4; ii++) {
                    float p = prow[ii*32 + j];
                    acc[ii][0] += p*w0.x; acc[ii][1] += p*w0.y;
                    acc[ii][2] += p*w0.z; acc[ii][3] += p*w0.w;
                    acc[ii][4] += p*w1.x; acc[ii][5] += p*w1.y;
                    acc[ii][6] += p*w1.z; acc[ii][7] += p*w1.w;
                }
            }
        }
    }
    __syncthreads();
#pragma unroll
    for (int m = 0; m < 4; m++) sDen[(ip*4+m)*8 + jg] = den[m];
    __syncthreads();
#pragma unroll
    for (int ii = 0; ii < 4; ii++) {
        int i = ig*4 + ii;
        float dsum = 0.f;
#pragma unroll
        for (int r = 0; r < 8; r++) dsum += sDen[(i*4+am)*8 + r];
        float inv = 1.f / fmaxf(dsum, 1e-30f);
        float o[8];
#pragma unroll
        for (int q = 0; q < 8; q++) {
            float v = acc[ii][q] * inv;
            o[q] = (v > 0.f) ? v : expm1f(v);   // ELU
        }
        float* dst = H + ((long)(b*NN) + i0 + i)*HC + am*192 + e*64 + g0;
        *(float4*)dst      = make_float4(o[0], o[1], o[2], o[3]);
        *(float4*)(dst+4)  = make_float4(o[4], o[5], o[6], o[7]);
    }
}

// ---------------- generic fp32 GEMM: C = alpha*(A@B) + beta*R, optional bn-stats ----------------
// 64x64 tile, 256 threads, 4x4 microtile, K-tile 16. M,N,K multiples of 64/64/16.
__global__ void __launch_bounds__(256) gemm_kernel(
        const float* __restrict__ A, const float* __restrict__ B, float* __restrict__ C,
        int M, int N, int K,
        long sA, long sB, long sC, int zDivA, int zModB,
        float alpha, const float* __restrict__ R, float beta,
        float* __restrict__ stats) {
    __shared__ float As[16][68];
    __shared__ float Bs[16][64];
    int z = blockIdx.z;
    A += (long)(z / zDivA) * sA;
    B += (long)(z % zModB) * sB;
    C += (long)z * sC;
    int n0 = blockIdx.x * 64, m0 = blockIdx.y * 64;
    int t = threadIdx.x;
    int tx = t & 15, ty = t >> 4;
    int la_m = t >> 2, la_k = (t & 3) * 4;
    int lb_k = t >> 4, lb_n = (t & 15) * 4;
    float acc[4][4] = {};
    for (int k0 = 0; k0 < K; k0 += 16) {
        float4 av = *(const float4*)(A + (long)(m0 + la_m)*K + k0 + la_k);
        float4 bv = *(const float4*)(B + (long)(k0 + lb_k)*N + n0 + lb_n);
        __syncthreads();
        As[la_k+0][la_m] = av.x; As[la_k+1][la_m] = av.y;
        As[la_k+2][la_m] = av.z; As[la_k+3][la_m] = av.w;
        *(float4*)&Bs[lb_k][lb_n] = bv;
        __syncthreads();
#pragma unroll
        for (int kk = 0; kk < 16; kk++) {
            float a0 = As[kk][ty*4+0], a1 = As[kk][ty*4+1];
            float a2 = As[kk][ty*4+2], a3 = As[kk][ty*4+3];
            float4 bq = *(float4*)&Bs[kk][tx*4];
            acc[0][0] += a0*bq.x; acc[0][1] += a0*bq.y; acc[0][2] += a0*bq.z; acc[0][3] += a0*bq.w;
            acc[1][0] += a1*bq.x; acc[1][1] += a1*bq.y; acc[1][2] += a1*bq.z; acc[1][3] += a1*bq.w;
            acc[2][0] += a2*bq.x; acc[2][1] += a2*bq.y; acc[2][2] += a2*bq.z; acc[2][3] += a2*bq.w;
            acc[3][0] += a3*bq.x; acc[3][1] += a3*bq.y; acc[3][2] += a3*bq.z; acc[3][3] += a3*bq.w;
        }
    }
    float csum[4] = {}, csq[4] = {};
#pragma unroll
    for (int i = 0; i < 4; i++) {
        long row = m0 + ty*4 + i;
        float v[4];
#pragma unroll
        for (int j = 0; j < 4; j++) v[j] = alpha * acc[i][j];
        if (R) {
            float4 r = *(const float4*)(R + row*N + n0 + tx*4);
            v[0] += beta*r.x; v[1] += beta*r.y; v[2] += beta*r.z; v[3] += beta*r.w;
        }
        *(float4*)(C + row*N + n0 + tx*4) = make_float4(v[0], v[1], v[2], v[3]);
        if (stats) {
#pragma unroll
            for (int j = 0; j < 4; j++) { csum[j] += v[j]; csq[j] += v[j]*v[j]; }
        }
    }
    if (stats) {
        __syncthreads();
        float* sS = &As[0][0];
        float* sQ = &Bs[0][0];
#pragma unroll
        for (int j = 0; j < 4; j++) {
            sS[(tx*4+j)*16 + ty] = csum[j];
            sQ[(tx*4+j)*16 + ty] = csq[j];
        }
        __syncthreads();
        if (t < 64) {
            float s = 0.f, q = 0.f;
#pragma unroll
            for (int r = 0; r < 16; r++) { s += sS[t*16+r]; q += sQ[t*16+r]; }
            atomicAdd(&stats[n0 + t], s);
            atomicAdd(&stats[N + n0 + t], q);
        }
    }
}

// ---------------- batchnorm normalize (+ optional ELU) ----------------
__global__ void norm_kernel(const float* __restrict__ Y, float* __restrict__ out,
                            const float* __restrict__ stats,
                            const float* __restrict__ g, const float* __restrict__ bb,
                            int N, int elu) {
    int idx = blockIdx.x*blockDim.x + threadIdx.x;
    if (idx >= ROWS*N) return;
    int col = idx & (N - 1);
    const float invM = 1.f / (float)ROWS;
    float mean = stats[col] * invM;
    float var  = stats[N + col] * invM - mean*mean;
    float w = g[col] * rsqrtf(var + 1e-5f);
    float v = (Y[idx] - mean) * w + bb[col];
    if (elu) v = (v > 0.f) ? v : expm1f(v);
    out[idx] = v;
}

// ---------------- launch ----------------
extern "C" void kernel_launch(void* const* d_in, const int* in_sizes, int n_in,
                              void* d_out, int out_size) {
    const int*   A      = (const int*)  d_in[0];
    const float* X      = (const float*)d_in[1];
    // d_in[2] = mini_batch (unused)
    const float* Ws     = (const float*)d_in[3];
    const float* a1     = (const float*)d_in[4];
    const float* a2     = (const float*)d_in[5];
    const float* W1     = (const float*)d_in[6];
    const float* bn1_g  = (const float*)d_in[7];
    const float* bn1_b  = (const float*)d_in[8];
    const float* e_l0   = (const float*)d_in[9];
    const float* e_bn0g = (const float*)d_in[10];
    const float* e_bn0b = (const float*)d_in[11];
    const float* e_l1   = (const float*)d_in[12];
    const float* e_bn1g = (const float*)d_in[13];
    const float* e_bn1b = (const float*)d_in[14];
    const float* e_l2   = (const float*)d_in[15];
    const float* bn2_g  = (const float*)d_in[16];
    const float* bn2_b  = (const float*)d_in[17];
    float* out = (float*)d_out;

    float *pWt, *pWh, *ps1, *ps2, *pH, *pHn, *pA, *pB, *pSt;
    cudaGetSymbolAddress((void**)&pWt, d_Wt);
    cudaGetSymbolAddress((void**)&pWh, d_Wh);
    cudaGetSymbolAddress((void**)&ps1, d_s1);
    cudaGetSymbolAddress((void**)&ps2, d_s2);
    cudaGetSymbolAddress((void**)&pH,  d_H);
    cudaGetSymbolAddress((void**)&pHn, d_Hn);
    cudaGetSymbolAddress((void**)&pA,  d_bufA);
    cudaGetSymbolAddress((void**)&pB,  d_bufB);
    cudaGetSymbolAddress((void**)&pSt, d_stats);

    cudaFuncSetAttribute(att_kernel, cudaFuncAttributeMaxDynamicSharedMemorySize, 53248);

    // zero bn-stat accumulators (must happen each replay)
    zero_kernel<<<8, 256>>>(pSt, 4*512);

    // edge_cat output (independent)
    edge_kernel<<<2048, 256>>>(A, out + ROWS*FF);

    // Ws relayout, Wh projection (batched GEMM over be), attention scores
    wt_kernel<<<384, 256>>>(Ws, pWt);
    gemm_kernel<<<dim3(SLOTS/64, NN/64, BE), 256>>>(
        X, pWt, pWh, NN, SLOTS, FF,
        (long)NN*FF, (long)FF*SLOTS, (long)NN*SLOTS, EE, EE,
        1.f, nullptr, 0.f, nullptr);
    s_kernel<<<3072, 256>>>(pWh, a1, a2, ps1, ps2);

    // fused masked softmax + P@Wh + ELU -> H
    att_kernel<<<dim3(32, BE), 256, 53248>>>(A, pWh, ps1, ps2, pH);

    // H @ W1 * 0.5 + 0.5*X  -> bufA, stats[0]; bn1 -> Hn
    gemm_kernel<<<dim3(FF/64, ROWS/64, 1), 256>>>(
        pH, W1, pA, ROWS, FF, HC, 0,0,0, 1,1,
        0.5f, X, 0.5f, pSt + 0);
    norm_kernel<<<(ROWS*FF+255)/256, 256>>>(pA, pHn, pSt + 0, bn1_g, bn1_b, FF, 0);

    // Hn @ e_l0 -> bufA, stats[1]; elu(bn) -> bufB
    gemm_kernel<<<dim3(L0C/64, ROWS/64, 1), 256>>>(
        pHn, e_l0, pA, ROWS, L0C, FF, 0,0,0, 1,1,
        1.f, nullptr, 0.f, pSt + 512);
    norm_kernel<<<(ROWS*L0C+255)/256, 256>>>(pA, pB, pSt + 512, e_bn0g, e_bn0b, L0C, 1);

    // Z0 @ e_l1 -> bufA, stats[2]; elu(bn) -> bufB
    gemm_kernel<<<dim3(L1C/64, ROWS/64, 1), 256>>>(
        pB, e_l1, pA, ROWS, L1C, L0C, 0,0,0, 1,1,
        1.f, nullptr, 0.f, pSt + 1024);
    norm_kernel<<<(ROWS*L1C+255)/256, 256>>>(pA, pB, pSt + 1024, e_bn1g, e_bn1b, L1C, 1);

    // Z1 @ e_l2 + Hn -> bufA, stats[3]; bn2 -> out[0 : ROWS*FF]
    gemm_kernel<<<dim3(FF/64, ROWS/64, 1), 256>>>(
        pB, e_l2, pA, ROWS, FF, L1C, 0,0,0, 1,1,
        1.f, pHn, 1.f, pSt + 1536);
    norm_kernel<<<(ROWS*FF+255)/256, 256>>>(pA, out, pSt + 1536, bn2_g, bn2_b, FF, 0);
}

// round 2
// speedup vs baseline: 1.8516x; 1.8516x over previous
#include <cuda_runtime.h>
#include <math.h>
#include <stdint.h>

// Problem constants
#define BB 8
#define NN 1024
#define FF 128
#define GG 64
#define MM 4
#define EE 3
#define BE (BB*EE)        // 24
#define SLOTS (MM*GG)     // 256
#define ROWS (BB*NN)      // 8192
#define HC (MM*EE*GG)     // 768
#define L0C 256
#define L1C 256

// ---------------- scratch (__device__ globals; no allocation allowed) ----------------
__device__ float d_Wt[EE*FF*SLOTS];          // Ws re-laid-out [e][f][m*64+g]
__device__ float d_Wh[BE*NN*SLOTS];          // [be][n][m*64+g]
__device__ float d_s1[BE*MM*NN];             // [be][m][n]
__device__ float d_s2[BE*MM*NN];
__device__ float d_H [ROWS*HC];              // [b*N+n][m*192+e*64+g]
__device__ float d_Hn[ROWS*FF];              // bn1 output
__device__ float d_bufA[ROWS*L0C];
__device__ float d_bufB[ROWS*L0C];
__device__ float d_stats[4*512];             // 4 layers x (sum[256] | sumsq[256])

__device__ __forceinline__ float tf32r(float x) {
    uint32_t u; asm("cvt.rna.tf32.f32 %0, %1;" : "=r"(u) : "f"(x));
    return __uint_as_float(u);
}

__device__ __forceinline__ void mma_tf32(float* d, const uint32_t* a, uint32_t b0, uint32_t b1) {
    asm volatile(
        "mma.sync.aligned.m16n8k8.row.col.f32.tf32.tf32.f32 "
        "{%0,%1,%2,%3}, {%4,%5,%6,%7}, {%8,%9}, {%0,%1,%2,%3};"
        : "+f"(d[0]), "+f"(d[1]), "+f"(d[2]), "+f"(d[3])
        : "r"(a[0]), "r"(a[1]), "r"(a[2]), "r"(a[3]), "r"(b0), "r"(b1));
}

// ---------------- tiny utility kernels ----------------
__global__ void zero_kernel(float* p, int n) {
    int i = blockIdx.x*blockDim.x + threadIdx.x;
    if (i < n) p[i] = 0.f;
}

// Wt[e][f][m*64+g] = Ws[e][(m*128+f)*64+g]
__global__ void wt_kernel(const float* __restrict__ Ws, float* __restrict__ Wt) {
    int idx = blockIdx.x*blockDim.x + threadIdx.x;
    if (idx >= EE*FF*SLOTS) return;
    int e = idx >> 15;
    int r = idx & 32767;
    int f = r >> 8;
    int c = r & 255;
    int m = c >> 6, g = c & 63;
    Wt[idx] = Ws[e*32768 + m*8192 + f*64 + g];
}

// edge_cat[b,i,j,e] = (float)A[b,e,i,j]
__global__ void edge_kernel(const int* __restrict__ A, float* __restrict__ out) {
    int idx = blockIdx.x*blockDim.x + threadIdx.x;
    if (idx >= BB*NN*(NN/16)) return;
    int j0 = (idx & 63) << 4;
    int bi = idx >> 6;
    int b = bi >> 10, i = bi & 1023;
    float v[48];
#pragma unroll
    for (int e = 0; e < 3; e++) {
        const int4* src = (const int4*)(A + (((long)(b*3+e)*NN + i) << 10) + j0);
#pragma unroll
        for (int k = 0; k < 4; k++) {
            int4 a = src[k];
            v[(k*4+0)*3+e] = (float)a.x;
            v[(k*4+1)*3+e] = (float)a.y;
            v[(k*4+2)*3+e] = (float)a.z;
            v[(k*4+3)*3+e] = (float)a.w;
        }
    }
    float4* o = (float4*)(out + (long)bi*3072 + (long)j0*3);
#pragma unroll
    for (int k = 0; k < 12; k++) o[k] = ((float4*)v)[k];
}

// s1[be][m][n] = sum_g Wh[be][n][m*64+g]*a1[e][m*64+g]
__global__ void s_kernel(const float* __restrict__ Wh, const float* __restrict__ a1,
                         const float* __restrict__ a2,
                         float* __restrict__ s1, float* __restrict__ s2) {
    int gtid = blockIdx.x*blockDim.x + threadIdx.x;
    int wid = gtid >> 5;
    int lane = gtid & 31;
    if (wid >= BE*NN) return;
    int be = wid >> 10;
    int n  = wid & 1023;
    int e  = be % 3;
    const float4* w  = (const float4*)(Wh + (long)wid*SLOTS);
    const float4* A1 = (const float4*)(a1 + e*SLOTS);
    const float4* A2 = (const float4*)(a2 + e*SLOTS);
    float4 wa = w[lane*2], wb = w[lane*2+1];
    float4 p1a = A1[lane*2], p1b = A1[lane*2+1];
    float4 p2a = A2[lane*2], p2b = A2[lane*2+1];
    float d1 = wa.x*p1a.x + wa.y*p1a.y + wa.z*p1a.z + wa.w*p1a.w
             + wb.x*p1b.x + wb.y*p1b.y + wb.z*p1b.z + wb.w*p1b.w;
    float d2 = wa.x*p2a.x + wa.y*p2a.y + wa.z*p2a.z + wa.w*p2a.w
             + wb.x*p2b.x + wb.y*p2b.y + wb.z*p2b.z + wb.w*p2b.w;
#pragma unroll
    for (int off = 4; off > 0; off >>= 1) {
        d1 += __shfl_down_sync(0xffffffffu, d1, off, 8);
        d2 += __shfl_down_sync(0xffffffffu, d2, off, 8);
    }
    if ((lane & 7) == 0) {
        int m = lane >> 3;
        s1[(be*4+m)*NN + n] = d1;
        s2[(be*4+m)*NN + n] = d2;
    }
}

// ---------------- attention v2: masked softmax + P@Wh via tf32 mma ----------------
// grid (16, 24): blockIdx.y = be, blockIdx.x = i-tile of 64 rows. 256 threads.
// smem floats: sWh[32][264] | sP[4][64][36] | sDen[256][4] | sDen2[256]
#define SWH_STRIDE 264
#define SP_STRIDE  36
#define SP_OFF     (32*SWH_STRIDE)                 // 8448
#define SDEN_OFF   (SP_OFF + 4*64*SP_STRIDE)       // 17664
#define SDEN2_OFF  (SDEN_OFF + 1024)               // 18688
#define ATT_SMEM_FLOATS (SDEN2_OFF + 256)          // 18944
#define ATT_SMEM_BYTES  (ATT_SMEM_FLOATS*4)        // 75776

__global__ void __launch_bounds__(256) att2_kernel(
        const int* __restrict__ A, const float* __restrict__ Wh,
        const float* __restrict__ s1, const float* __restrict__ s2,
        float* __restrict__ H) {
    extern __shared__ float sm[];
    float* sWh  = sm;
    float* sP   = sm + SP_OFF;
    float* sDen = sm + SDEN_OFF;
    float* sDen2= sm + SDEN2_OFF;

    const int be = blockIdx.y;
    const int b  = be / 3, e = be % 3;
    const int i0 = blockIdx.x * 64;
    const int t  = threadIdx.x;
    const int lane = t & 31;
    const int w  = t >> 5;
    const int gid = lane >> 2, tig = lane & 3;

    // p-phase mapping: ip = row (0..63), jg = j-chunk of 8 (0..3)
    const int ip = t >> 2;
    const int jg = t & 3;
    // mma mapping
    const int am = w >> 1;           // head 0..3
    const int nh = (w & 1) * 32;     // n-half within head's 64 g

    float s1v[4];
#pragma unroll
    for (int m = 0; m < 4; m++) s1v[m] = s1[(be*4+m)*NN + i0 + ip];

    float den[4] = {0.f,0.f,0.f,0.f};
    float acc[4][4][4];
#pragma unroll
    for (int mt = 0; mt < 4; mt++)
#pragma unroll
        for (int nt = 0; nt < 4; nt++)
#pragma unroll
            for (int q = 0; q < 4; q++) acc[mt][nt][q] = 0.f;

    const int*    Arow = A + ((long)be*NN + i0 + ip)*NN;
    const float4* WhB  = (const float4*)(Wh + (long)be*NN*SLOTS);
    const float*  s2b  = s2 + be*4*NN;

    for (int j0 = 0; j0 < NN; j0 += 32) {
        __syncthreads();
        // load Wh tile [32 j][256 slots] with tf32 rounding
        {
#pragma unroll
            for (int k = 0; k < 8; k++) {
                int idx = t + k*256;          // 0..2047
                int jj = idx >> 6;
                int cq = idx & 63;
                float4 v = WhB[(long)(j0+jj)*64 + cq];
                v.x = tf32r(v.x); v.y = tf32r(v.y);
                v.z = tf32r(v.z); v.w = tf32r(v.w);
                *(float4*)(sWh + jj*SWH_STRIDE + cq*4) = v;
            }
        }
        // p-phase: masked exp(lrelu(s1+s2)), 4 heads x 8 j per thread
        {
            int4 mk0 = *(const int4*)(Arow + j0 + jg*8);
            int4 mk1 = *(const int4*)(Arow + j0 + jg*8 + 4);
            int mv[8] = {mk0.x, mk0.y, mk0.z, mk0.w, mk1.x, mk1.y, mk1.z, mk1.w};
#pragma unroll
            for (int m = 0; m < 4; m++) {
                float4 sa = *(const float4*)(s2b + m*NN + j0 + jg*8);
                float4 sb = *(const float4*)(s2b + m*NN + j0 + jg*8 + 4);
                float sv[8] = {sa.x, sa.y, sa.z, sa.w, sb.x, sb.y, sb.z, sb.w};
                float pv[8];
#pragma unroll
                for (int q = 0; q < 8; q++) {
                    float x = s1v[m] + sv[q];
                    float l = (x >= 0.f) ? x : 0.01f*x;
                    float p = (mv[q] > 0) ? __expf(l) : 0.f;
                    den[m] += p;
                    pv[q] = tf32r(p);
                }
                float* d = sP + (m*64 + ip)*SP_STRIDE + jg*8;
                *(float4*)d     = make_float4(pv[0], pv[1], pv[2], pv[3]);
                *(float4*)(d+4) = make_float4(pv[4], pv[5], pv[6], pv[7]);
            }
        }
        __syncthreads();
        // mma phase: per warp, head am, n-half nh: P[64x32] @ Wh[32x32]
        {
            const float* Pm = sP + am*64*SP_STRIDE;
            const float* Wc = sWh + am*64 + nh;
#pragma unroll
            for (int ks = 0; ks < 4; ks++) {
                int k0 = ks*8;
                uint32_t bf[4][2];
#pragma unroll
                for (int nt = 0; nt < 4; nt++) {
                    bf[nt][0] = __float_as_uint(Wc[(k0+tig)*SWH_STRIDE + nt*8 + gid]);
                    bf[nt][1] = __float_as_uint(Wc[(k0+tig+4)*SWH_STRIDE + nt*8 + gid]);
                }
#pragma unroll
                for (int mt = 0; mt < 4; mt++) {
                    const float* pr = Pm + (mt*16 + gid)*SP_STRIDE + k0 + tig;
                    uint32_t af[4];
                    af[0] = __float_as_uint(pr[0]);
                    af[2] = __float_as_uint(pr[4]);
                    af[1] = __float_as_uint(pr[8*SP_STRIDE]);
                    af[3] = __float_as_uint(pr[8*SP_STRIDE + 4]);
#pragma unroll
                    for (int nt = 0; nt < 4; nt++)
                        mma_tf32(acc[mt][nt], af, bf[nt][0], bf[nt][1]);
                }
            }
        }
    }
    // denominator reduce
    __syncthreads();
#pragma unroll
    for (int m = 0; m < 4; m++) sDen[(m*64 + ip)*4 + jg] = den[m];
    __syncthreads();
    {
        float s = sDen[t*4] + sDen[t*4+1] + sDen[t*4+2] + sDen[t*4+3];
        sDen2[t] = 1.f / fmaxf(s, 1e-30f);
    }
    __syncthreads();
    // epilogue: normalize, ELU, store
#pragma unroll
    for (int mt = 0; mt < 4; mt++) {
        int r0 = mt*16 + gid;
        float inv0 = sDen2[am*64 + r0];
        float inv1 = sDen2[am*64 + r0 + 8];
        long row0 = (long)(b*NN) + i0 + r0;
        long row1 = row0 + 8;
#pragma unroll
        for (int nt = 0; nt < 4; nt++) {
            int col = am*192 + e*64 + nh + nt*8 + 2*tig;
            float v0 = acc[mt][nt][0]*inv0, v1 = acc[mt][nt][1]*inv0;
            float v2 = acc[mt][nt][2]*inv1, v3 = acc[mt][nt][3]*inv1;
            v0 = (v0 > 0.f) ? v0 : expm1f(v0);
            v1 = (v1 > 0.f) ? v1 : expm1f(v1);
            v2 = (v2 > 0.f) ? v2 : expm1f(v2);
            v3 = (v3 > 0.f) ? v3 : expm1f(v3);
            *(float2*)(H + row0*HC + col) = make_float2(v0, v1);
            *(float2*)(H + row1*HC + col) = make_float2(v2, v3);
        }
    }
}

// ---------------- tf32 mma GEMM: C = alpha*(A@B) + beta*R, optional bn-stats ----------------
// 64x64 tile, k-tile 32, 8 warps each 16m x 32n. M%64==0, N%64==0, K%32==0.
__global__ void __launch_bounds__(256) gemm2_kernel(
        const float* __restrict__ A, const float* __restrict__ B, float* __restrict__ C,
        int M, int N, int K,
        long sA, long sB, long sC, int zDivA, int zModB,
        float alpha, const float* __restrict__ R, float beta,
        float* __restrict__ stats) {
    __shared__ float As[64*36];
    __shared__ float Bs[32*72];
    int z = blockIdx.z;
    A += (long)(z / zDivA) * sA;
    B += (long)(z % zModB) * sB;
    C += (long)z * sC;
    int n0 = blockIdx.x * 64, m0 = blockIdx.y * 64;
    int t = threadIdx.x, lane = t & 31, w = t >> 5;
    int gid = lane >> 2, tig = lane & 3;
    int mrow = (w & 3) * 16, ncol = (w >> 2) * 32;
    float acc[4][4];
#pragma unroll
    for (int nt = 0; nt < 4; nt++)
#pragma unroll
        for (int q = 0; q < 4; q++) acc[nt][q] = 0.f;

    for (int k0 = 0; k0 < K; k0 += 32) {
        __syncthreads();
#pragma unroll
        for (int p = 0; p < 2; p++) {
            int idx = t + p*256;
            int m = idx >> 3, kq = (idx & 7) * 4;
            float4 v = *(const float4*)(A + (long)(m0 + m)*K + k0 + kq);
            v.x = tf32r(v.x); v.y = tf32r(v.y); v.z = tf32r(v.z); v.w = tf32r(v.w);
            *(float4*)(As + m*36 + kq) = v;
            int kk = idx >> 4, nq = (idx & 15) * 4;
            float4 u = *(const float4*)(B + (long)(k0 + kk)*N + n0 + nq);
            u.x = tf32r(u.x); u.y = tf32r(u.y); u.z = tf32r(u.z); u.w = tf32r(u.w);
            *(float4*)(Bs + kk*72 + nq) = u;
        }
        __syncthreads();
#pragma unroll
        for (int ks = 0; ks < 4; ks++) {
            int kb = ks*8;
            const float* ap = As + (mrow + gid)*36 + kb + tig;
            uint32_t af[4];
            af[0] = __float_as_uint(ap[0]);
            af[2] = __float_as_uint(ap[4]);
            af[1] = __float_as_uint(ap[8*36]);
            af[3] = __float_as_uint(ap[8*36 + 4]);
#pragma unroll
            for (int nt = 0; nt < 4; nt++) {
                uint32_t b0 = __float_as_uint(Bs[(kb+tig)*72 + ncol + nt*8 + gid]);
                uint32_t b1 = __float_as_uint(Bs[(kb+tig+4)*72 + ncol + nt*8 + gid]);
                mma_tf32(acc[nt], af, b0, b1);
            }
        }
    }
    // epilogue (fragment layout)
    float stS[4][2], stQ[4][2];
    long r0 = m0 + mrow + gid, r1 = r0 + 8;
#pragma unroll
    for (int nt = 0; nt < 4; nt++) {
        int c = n0 + ncol + nt*8 + 2*tig;
        float v0 = alpha*acc[nt][0], v1 = alpha*acc[nt][1];
        float v2 = alpha*acc[nt][2], v3 = alpha*acc[nt][3];
        if (R) {
            float2 ra = *(const float2*)(R + r0*N + c);
            float2 rb = *(const float2*)(R + r1*N + c);
            v0 += beta*ra.x; v1 += beta*ra.y; v2 += beta*rb.x; v3 += beta*rb.y;
        }
        *(float2*)(C + r0*N + c) = make_float2(v0, v1);
        *(float2*)(C + r1*N + c) = make_float2(v2, v3);
        stS[nt][0] = v0 + v2; stS[nt][1] = v1 + v3;
        stQ[nt][0] = v0*v0 + v2*v2; stQ[nt][1] = v1*v1 + v3*v3;
    }
    if (stats) {
#pragma unroll
        for (int nt = 0; nt < 4; nt++) {
#pragma unroll
            for (int cc = 0; cc < 2; cc++) {
                float s = stS[nt][cc], q = stQ[nt][cc];
#pragma unroll
                for (int off = 16; off >= 4; off >>= 1) {
                    s += __shfl_down_sync(0xffffffffu, s, off);
                    q += __shfl_down_sync(0xffffffffu, q, off);
                }
                if (lane < 4) {
                    int col = n0 + ncol + nt*8 + 2*lane + cc;
                    atomicAdd(&stats[col], s);
                    atomicAdd(&stats[N + col], q);
                }
            }
        }
    }
}

// ---------------- batchnorm normalize (+ optional ELU) ----------------
__global__ void norm_kernel(const float* __restrict__ Y, float* __restrict__ out,
                            const float* __restrict__ stats,
                            const float* __restrict__ g, const float* __restrict__ bb,
                            int N, int elu) {
    int idx = blockIdx.x*blockDim.x + threadIdx.x;
    if (idx >= ROWS*N) return;
    int col = idx & (N - 1);
    const float invM = 1.f / (float)ROWS;
    float mean = stats[col] * invM;
    float var  = stats[N + col] * invM - mean*mean;
    float ww = g[col] * rsqrtf(var + 1e-5f);
    float v = (Y[idx] - mean) * ww + bb[col];
    if (elu) v = (v > 0.f) ? v : expm1f(v);
    out[idx] = v;
}

// ---------------- launch ----------------
extern "C" void kernel_launch(void* const* d_in, const int* in_sizes, int n_in,
                              void* d_out, int out_size) {
    const int*   A      = (const int*)  d_in[0];
    const float* X      = (const float*)d_in[1];
    const float* Ws     = (const float*)d_in[3];
    const float* a1     = (const float*)d_in[4];
    const float* a2     = (const float*)d_in[5];
    const float* W1     = (const float*)d_in[6];
    const float* bn1_g  = (const float*)d_in[7];
    const float* bn1_b  = (const float*)d_in[8];
    const float* e_l0   = (const float*)d_in[9];
    const float* e_bn0g = (const float*)d_in[10];
    const float* e_bn0b = (const float*)d_in[11];
    const float* e_l1   = (const float*)d_in[12];
    const float* e_bn1g = (const float*)d_in[13];
    const float* e_bn1b = (const float*)d_in[14];
    const float* e_l2   = (const float*)d_in[15];
    const float* bn2_g  = (const float*)d_in[16];
    const float* bn2_b  = (const float*)d_in[17];
    float* out = (float*)d_out;

    float *pWt, *pWh, *ps1, *ps2, *pH, *pHn, *pA, *pB, *pSt;
    cudaGetSymbolAddress((void**)&pWt, d_Wt);
    cudaGetSymbolAddress((void**)&pWh, d_Wh);
    cudaGetSymbolAddress((void**)&ps1, d_s1);
    cudaGetSymbolAddress((void**)&ps2, d_s2);
    cudaGetSymbolAddress((void**)&pH,  d_H);
    cudaGetSymbolAddress((void**)&pHn, d_Hn);
    cudaGetSymbolAddress((void**)&pA,  d_bufA);
    cudaGetSymbolAddress((void**)&pB,  d_bufB);
    cudaGetSymbolAddress((void**)&pSt, d_stats);

    cudaFuncSetAttribute(att2_kernel, cudaFuncAttributeMaxDynamicSharedMemorySize, ATT_SMEM_BYTES);

    // zero bn-stat accumulators (must happen each replay)
    zero_kernel<<<8, 256>>>(pSt, 4*512);

    // edge_cat output (independent)
    edge_kernel<<<2048, 256>>>(A, out + ROWS*FF);

    // Ws relayout, Wh projection (batched GEMM over be), attention scores
    wt_kernel<<<384, 256>>>(Ws, pWt);
    gemm2_kernel<<<dim3(SLOTS/64, NN/64, BE), 256>>>(
        X, pWt, pWh, NN, SLOTS, FF,
        (long)NN*FF, (long)FF*SLOTS, (long)NN*SLOTS, EE, EE,
        1.f, nullptr, 0.f, nullptr);
    s_kernel<<<3072, 256>>>(pWh, a1, a2, ps1, ps2);

    // fused masked softmax + P@Wh + ELU -> H (tf32 mma)
    att2_kernel<<<dim3(NN/64, BE), 256, ATT_SMEM_BYTES>>>(A, pWh, ps1, ps2, pH);

    // H @ W1 * 0.5 + 0.5*X -> bufA, stats[0]; bn1 -> Hn
    gemm2_kernel<<<dim3(FF/64, ROWS/64, 1), 256>>>(
        pH, W1, pA, ROWS, FF, HC, 0,0,0, 1,1,
        0.5f, X, 0.5f, pSt + 0);
    norm_kernel<<<(ROWS*FF+255)/256, 256>>>(pA, pHn, pSt + 0, bn1_g, bn1_b, FF, 0);

    // Hn @ e_l0 -> bufA, stats[1]; elu(bn) -> bufB
    gemm2_kernel<<<dim3(L0C/64, ROWS/64, 1), 256>>>(
        pHn, e_l0, pA, ROWS, L0C, FF, 0,0,0, 1,1,
        1.f, nullptr, 0.f, pSt + 512);
    norm_kernel<<<(ROWS*L0C+255)/256, 256>>>(pA, pB, pSt + 512, e_bn0g, e_bn0b, L0C, 1);

    // Z0 @ e_l1 -> bufA, stats[2]; elu(bn) -> bufB
    gemm2_kernel<<<dim3(L1C/64, ROWS/64, 1), 256>>>(
        pB, e_l1, pA, ROWS, L1C, L0C, 0,0,0, 1,1,
        1.f, nullptr, 0.f, pSt + 1024);
    norm_kernel<<<(ROWS*L1C+255)/256, 256>>>(pA, pB, pSt + 1024, e_bn1g, e_bn1b, L1C, 1);

    // Z1 @ e_l2 + Hn -> bufA, stats[3]; bn2 -> out[0 : ROWS*FF]
    gemm2_kernel<<<dim3(FF/64, ROWS/64, 1), 256>>>(
        pB, e_l2, pA, ROWS, FF, L1C, 0,0,0, 1,1,
        1.f, pHn, 1.f, pSt + 1536);
    norm_kernel<<<(ROWS*FF+255)/256, 256>>>(pA, out, pSt + 1536, bn2_g, bn2_b, FF, 0);
}